// round 14
// baseline (speedup 1.0000x reference)
#include <cuda_runtime.h>
#include <math.h>

// Problem constants: B=32, C=3, H=W=512
#define BB 32
#define CC 3
#define HH 512
#define WW 512
#define PX 4   // pixels per thread, warp-interleaved (stride 32)

// Fused kernel with warp-uniform three-way specialization:
//   dead     -> zero-fill fast path (R13)
//   interior -> branch-free body: no masks, unconditional front-batched loads
//   boundary -> guarded-load body (R8)
// All branches are warp-uniform (endpoint tests on an affine, monotone-in-X map).
__global__ __launch_bounds__(256, 8) void warp_kernel(const float* __restrict__ x,
                                                      const float* __restrict__ thetas,
                                                      const float* __restrict__ l1s,
                                                      const float* __restrict__ l2s,
                                                      float* __restrict__ out) {
    int lane    = threadIdx.x;                        // 0..31
    int b       = blockIdx.z;
    int px_base = blockIdx.x * (32 * PX);             // 128-px segment in x
    int py      = blockIdx.y * 8 + threadIdx.y;       // this warp's row
    int px0     = px_base + lane;

    // theta matrix (translation exactly zero); uniform within the CTA
    float th = -__ldg(thetas + b);
    float c, s;
    __sincosf(th, &s, &c);
    float il1 = 1.0f / __ldg(l1s + b);
    float il2 = 1.0f / __ldg(l2s + b);
    float m00 = c * c * il1 + s * s * il2;
    float m11 = s * s * il1 + c * c * il2;
    float m01 = c * s * (il2 - il1);

    float Y = ((float)py + 0.5f) * (2.0f / (float)HH) - 1.0f;

    // ---- warp-uniform segment bounds (endpoints in X; affine & monotone) ----
    float Xlo = ((float)px_base + 0.5f)   * (2.0f / WW) - 1.0f;
    float Xhi = ((float)px_base + 127.5f) * (2.0f / WW) - 1.0f;

    float gx_lo = (m00 * Xlo + m01 * Y + 1.0f) * (WW * 0.5f) - 0.5f;  // min (m00>0)
    float gx_hi = (m00 * Xhi + m01 * Y + 1.0f) * (WW * 0.5f) - 0.5f;  // max
    float gyA   = (m01 * Xlo + m11 * Y + 1.0f) * (HH * 0.5f) - 0.5f;
    float gyB   = (m01 * Xhi + m11 * Y + 1.0f) * (HH * 0.5f) - 0.5f;
    float gy_lo = fminf(gyA, gyB);
    float gy_hi = fmaxf(gyA, gyB);

    // ---- dead segment: zero-fill and exit ----
    {
        const float MARGIN = 1e-3f;
        bool dead = (gx_hi < -1.0f - MARGIN) | (gx_lo >= (float)WW + MARGIN) |
                    (gy_hi < -1.0f - MARGIN) | (gy_lo >= (float)HH + MARGIN);
        if (dead) {
            float4 z = make_float4(0.f, 0.f, 0.f, 0.f);
            float4* dst = (float4*)(out + ((size_t)b * CC) * HH * WW +
                                    (size_t)py * WW + px_base) + lane;
#pragma unroll
            for (int cc = 0; cc < CC; cc++)
                __stcs(dst + cc * (HH * WW / 4), z);
            return;
        }
    }

    float X = ((float)px0 + 0.5f) * (2.0f / (float)WW) - 1.0f;
    float gx = (m00 * X + m01 * Y + 1.0f) * ((float)WW * 0.5f) - 0.5f;
    float gy = (m01 * X + m11 * Y + 1.0f) * ((float)HH * 0.5f) - 0.5f;
    float sx = 32.0f * m00;
    float sy = 32.0f * m01;

    const float* xb = x + (size_t)b * CC * HH * WW;
    float* ob = out + ((size_t)b * CC) * HH * WW + (size_t)py * WW + px0;

    // ---- fully-interior segment: branch-free, unconditional loads ----
    {
        const float IM = 1e-2f;   // conservative inward margin vs fp drift
        bool interior = (gx_lo > IM) & (gx_hi < (float)(WW - 1) - IM) &
                        (gy_lo > IM) & (gy_hi < (float)(HH - 1) - IM);
        if (interior) {
            float w00[PX], w01[PX], w10[PX], w11[PX];
            int   i00[PX];
#pragma unroll
            for (int k = 0; k < PX; k++) {
                float x0f = floorf(gx);
                float y0f = floorf(gy);
                float wx1 = gx - x0f;
                float wy1 = gy - y0f;
                float wx0 = 1.0f - wx1;
                float wy0 = 1.0f - wy1;
                w00[k] = wy0 * wx0;
                w01[k] = wy0 * wx1;
                w10[k] = wy1 * wx0;
                w11[k] = wy1 * wx1;
                i00[k] = (int)y0f * WW + (int)x0f;
                gx += sx;
                gy += sy;
            }
#pragma unroll
            for (int cc = 0; cc < CC; cc++) {
                const float* p = xb + (size_t)cc * HH * WW;
                float v[PX];
#pragma unroll
                for (int k = 0; k < PX; k++) {
                    int i0 = i00[k];
                    v[k] = w00[k] * __ldg(p + i0) +
                           w01[k] * __ldg(p + i0 + 1) +
                           w10[k] * __ldg(p + i0 + WW) +
                           w11[k] * __ldg(p + i0 + WW + 1);
                }
                float* oc = ob + (size_t)cc * HH * WW;
#pragma unroll
                for (int k = 0; k < PX; k++)
                    oc[32 * k] = v[k];
            }
            return;
        }
    }

    // ---- boundary segment: guarded loads (R8 body) ----
    {
        float w00[PX], w01[PX], w10[PX], w11[PX];
        int   i00[PX];
#pragma unroll
        for (int k = 0; k < PX; k++) {
            float x0f = floorf(gx);
            float y0f = floorf(gy);
            int x0 = (int)x0f;
            int y0 = (int)y0f;

            float wx1 = gx - x0f;
            float wx0 = 1.0f - wx1;
            float wy1 = gy - y0f;
            float wy0 = 1.0f - wy1;

            float cx0 = ((unsigned)x0       < (unsigned)WW) ? wx0 : 0.0f;
            float cx1 = ((unsigned)(x0 + 1) < (unsigned)WW) ? wx1 : 0.0f;
            float cy0 = ((unsigned)y0       < (unsigned)HH) ? wy0 : 0.0f;
            float cy1 = ((unsigned)(y0 + 1) < (unsigned)HH) ? wy1 : 0.0f;

            w00[k] = cy0 * cx0;
            w01[k] = cy0 * cx1;
            w10[k] = cy1 * cx0;
            w11[k] = cy1 * cx1;

            i00[k] = y0 * WW + x0;

            gx += sx;
            gy += sy;
        }

#pragma unroll
        for (int cc = 0; cc < CC; cc++) {
            const float* p = xb + (size_t)cc * HH * WW;
            float v[PX];
#pragma unroll
            for (int k = 0; k < PX; k++) {
                int i0 = i00[k];
                float acc = 0.0f;
                if (w00[k] != 0.0f) acc += w00[k] * __ldg(p + i0);
                if (w01[k] != 0.0f) acc += w01[k] * __ldg(p + i0 + 1);
                if (w10[k] != 0.0f) acc += w10[k] * __ldg(p + i0 + WW);
                if (w11[k] != 0.0f) acc += w11[k] * __ldg(p + i0 + WW + 1);
                v[k] = acc;
            }
            float* oc = ob + (size_t)cc * HH * WW;
#pragma unroll
            for (int k = 0; k < PX; k++)
                oc[32 * k] = v[k];
        }
    }
}

extern "C" void kernel_launch(void* const* d_in, const int* in_sizes, int n_in,
                              void* d_out, int out_size) {
    const float* x      = (const float*)d_in[0];
    const float* thetas = (const float*)d_in[1];
    const float* l1s    = (const float*)d_in[2];
    const float* l2s    = (const float*)d_in[3];
    float* out = (float*)d_out;

    dim3 block(32, 8, 1);
    dim3 grid(WW / (32 * PX), HH / 8, BB);   // 4 x 64 x 32 = 8192 CTAs
    warp_kernel<<<grid, block>>>(x, thetas, l1s, l2s, out);
}

// round 15
// speedup vs baseline: 1.0414x; 1.0414x over previous
#include <cuda_runtime.h>
#include <math.h>

// Problem constants: B=32, C=3, H=W=512
#define BB 32
#define CC 3
#define HH 512
#define WW 512
#define PX 4   // pixels per thread, warp-interleaved (stride 32)

// Fused kernel, R13 structure: warp-uniform dead-segment zero-fill, then the
// guarded-gather body. All output stores are streaming (__stcs) so the 100MB
// write stream does not evict gather input from L2. 4-warp CTAs for balance.
__global__ __launch_bounds__(128, 16) void warp_kernel(const float* __restrict__ x,
                                                       const float* __restrict__ thetas,
                                                       const float* __restrict__ l1s,
                                                       const float* __restrict__ l2s,
                                                       float* __restrict__ out) {
    int lane    = threadIdx.x;                        // 0..31
    int b       = blockIdx.z;
    int px_base = blockIdx.x * (32 * PX);             // 128-px segment in x
    int py      = blockIdx.y * 4 + threadIdx.y;       // this warp's row
    int px0     = px_base + lane;

    // theta matrix (translation exactly zero); uniform within the CTA
    float th = -__ldg(thetas + b);
    float c, s;
    __sincosf(th, &s, &c);
    float il1 = 1.0f / __ldg(l1s + b);
    float il2 = 1.0f / __ldg(l2s + b);
    float m00 = c * c * il1 + s * s * il2;
    float m11 = s * s * il1 + c * c * il2;
    float m01 = c * s * (il2 - il1);

    float Y = ((float)py + 0.5f) * (2.0f / (float)HH) - 1.0f;

    // ---- warp-uniform fully-OOB segment test (endpoints in X) ----
    {
        float Xlo = ((float)px_base + 0.5f)   * (2.0f / WW) - 1.0f;
        float Xhi = ((float)px_base + 127.5f) * (2.0f / WW) - 1.0f;

        float gx_lo = (m00 * Xlo + m01 * Y + 1.0f) * (WW * 0.5f) - 0.5f;  // min (m00>0)
        float gx_hi = (m00 * Xhi + m01 * Y + 1.0f) * (WW * 0.5f) - 0.5f;  // max
        float gyA   = (m01 * Xlo + m11 * Y + 1.0f) * (HH * 0.5f) - 0.5f;
        float gyB   = (m01 * Xhi + m11 * Y + 1.0f) * (HH * 0.5f) - 0.5f;
        float gy_lo = fminf(gyA, gyB);
        float gy_hi = fmaxf(gyA, gyB);

        const float MARGIN = 1e-3f;
        bool dead = (gx_hi < -1.0f - MARGIN) | (gx_lo >= (float)WW + MARGIN) |
                    (gy_hi < -1.0f - MARGIN) | (gy_lo >= (float)HH + MARGIN);
        if (dead) {   // uniform across the warp — no divergence
            float4 z = make_float4(0.f, 0.f, 0.f, 0.f);
            float4* dst = (float4*)(out + ((size_t)b * CC) * HH * WW +
                                    (size_t)py * WW + px_base) + lane;
#pragma unroll
            for (int cc = 0; cc < CC; cc++)
                __stcs(dst + cc * (HH * WW / 4), z);
            return;
        }
    }

    float X = ((float)px0 + 0.5f) * (2.0f / (float)WW) - 1.0f;
    float gx = (m00 * X + m01 * Y + 1.0f) * ((float)WW * 0.5f) - 0.5f;
    float gy = (m01 * X + m11 * Y + 1.0f) * ((float)HH * 0.5f) - 0.5f;
    float sx = 32.0f * m00;
    float sy = 32.0f * m01;

    float w00[PX], w01[PX], w10[PX], w11[PX];
    int   i00[PX];

#pragma unroll
    for (int k = 0; k < PX; k++) {
        float x0f = floorf(gx);
        float y0f = floorf(gy);
        int x0 = (int)x0f;
        int y0 = (int)y0f;

        float wx1 = gx - x0f;
        float wx0 = 1.0f - wx1;
        float wy1 = gy - y0f;
        float wy0 = 1.0f - wy1;

        // fold border masks into the 1D weights (one unsigned compare each)
        float cx0 = ((unsigned)x0       < (unsigned)WW) ? wx0 : 0.0f;
        float cx1 = ((unsigned)(x0 + 1) < (unsigned)WW) ? wx1 : 0.0f;
        float cy0 = ((unsigned)y0       < (unsigned)HH) ? wy0 : 0.0f;
        float cy1 = ((unsigned)(y0 + 1) < (unsigned)HH) ? wy1 : 0.0f;

        w00[k] = cy0 * cx0;
        w01[k] = cy0 * cx1;
        w10[k] = cy1 * cx0;
        w11[k] = cy1 * cx1;

        i00[k] = y0 * WW + x0;   // raw index; loads are weight-guarded

        gx += sx;
        gy += sy;
    }

    const float* xb = x + (size_t)b * CC * HH * WW;
    float* ob = out + ((size_t)b * CC) * HH * WW + (size_t)py * WW + px0;

#pragma unroll
    for (int cc = 0; cc < CC; cc++) {
        const float* p = xb + (size_t)cc * HH * WW;
        float v[PX];
#pragma unroll
        for (int k = 0; k < PX; k++) {
            int i0 = i00[k];
            float acc = 0.0f;
            if (w00[k] != 0.0f) acc += w00[k] * __ldg(p + i0);
            if (w01[k] != 0.0f) acc += w01[k] * __ldg(p + i0 + 1);
            if (w10[k] != 0.0f) acc += w10[k] * __ldg(p + i0 + WW);
            if (w11[k] != 0.0f) acc += w11[k] * __ldg(p + i0 + WW + 1);
            v[k] = acc;
        }
        float* oc = ob + (size_t)cc * HH * WW;
#pragma unroll
        for (int k = 0; k < PX; k++)
            __stcs(oc + 32 * k, v[k]);
    }
}

extern "C" void kernel_launch(void* const* d_in, const int* in_sizes, int n_in,
                              void* d_out, int out_size) {
    const float* x      = (const float*)d_in[0];
    const float* thetas = (const float*)d_in[1];
    const float* l1s    = (const float*)d_in[2];
    const float* l2s    = (const float*)d_in[3];
    float* out = (float*)d_out;

    dim3 block(32, 4, 1);
    dim3 grid(WW / (32 * PX), HH / 4, BB);   // 4 x 128 x 32 = 16384 CTAs
    warp_kernel<<<grid, block>>>(x, thetas, l1s, l2s, out);
}